// round 14
// baseline (speedup 1.0000x reference)
#include <cuda_runtime.h>
#include <cuda_bf16.h>
#include <cstdint>

#define NB     4
#define CIN    64
#define COUT   128
#define NPATCH 4096
#define KDIM   1024

// im2col + split operands
__device__ __nv_bfloat16 g_xh[NB * NPATCH * KDIM];   // [b][n][k]
__device__ __nv_bfloat16 g_xl[NB * NPATCH * KDIM];
__device__ __nv_bfloat16 g_wh[3 * COUT * KDIM];      // [mat][o][k]
__device__ __nv_bfloat16 g_wl[3 * COUT * KDIM];
// q/k/v split operands produced by conv_mma
__device__ __nv_bfloat16 g_qh[NB * NPATCH * COUT];   // [b][n][o]
__device__ __nv_bfloat16 g_ql[NB * NPATCH * COUT];
__device__ __nv_bfloat16 g_kh[NB * NPATCH * COUT];   // [b][n][o]
__device__ __nv_bfloat16 g_kl[NB * NPATCH * COUT];
__device__ __nv_bfloat16 g_vh[NB * COUT * NPATCH];   // [b][o][n]  (transposed)
__device__ __nv_bfloat16 g_vl[NB * COUT * NPATCH];

// ---------------- warp-level tensor core helpers (baseline PTX, sm_80+) ------
#define LDSM_X4(r0, r1, r2, r3, addr) \
    asm volatile("ldmatrix.sync.aligned.m8n8.x4.shared.b16 {%0,%1,%2,%3}, [%4];" \
        : "=r"(r0), "=r"(r1), "=r"(r2), "=r"(r3) : "r"(addr))
#define CP_ASYNC16(saddr, gptr) \
    asm volatile("cp.async.cg.shared.global [%0], [%1], 16;" :: "r"(saddr), "l"(gptr))
#define CP_COMMIT() asm volatile("cp.async.commit_group;" ::: "memory")
#define CP_WAIT0()  asm volatile("cp.async.wait_group 0;" ::: "memory")

__device__ __forceinline__ void mma16816(float c[4],
    uint32_t a0, uint32_t a1, uint32_t a2, uint32_t a3,
    uint32_t b0, uint32_t b1)
{
    asm volatile(
        "mma.sync.aligned.m16n8k16.row.col.f32.bf16.bf16.f32 "
        "{%0,%1,%2,%3}, {%4,%5,%6,%7}, {%8,%9}, {%0,%1,%2,%3};"
        : "+f"(c[0]), "+f"(c[1]), "+f"(c[2]), "+f"(c[3])
        : "r"(a0), "r"(a1), "r"(a2), "r"(a3), "r"(b0), "r"(b1));
}

__device__ __forceinline__ uint32_t smem_u32(const void* p) {
    uint32_t a;
    asm("{ .reg .u64 t; cvta.to.shared.u64 t, %1; cvt.u32.u64 %0, t; }" : "=r"(a) : "l"(p));
    return a;
}
// split two fp32 into bf16x2 hi + bf16x2 lo (residual)
__device__ __forceinline__ void split2(float x, float y, uint32_t& hi, uint32_t& lo) {
    __nv_bfloat16 hx = __float2bfloat16(x), hy = __float2bfloat16(y);
    __nv_bfloat162 h2(hx, hy);
    __nv_bfloat162 l2(__float2bfloat16(x - __bfloat162float(hx)),
                      __float2bfloat16(y - __bfloat162float(hy)));
    hi = *(uint32_t*)&h2;
    lo = *(uint32_t*)&l2;
}

// ---------------------------------------------------------------------------
// split_x / split_w  (unchanged)
// ---------------------------------------------------------------------------
__global__ void __launch_bounds__(256)
split_x_kernel(const float* __restrict__ x)
{
    const int ph = blockIdx.x, b = blockIdx.y;
    const int t  = threadIdx.x;
    const int kh = t >> 6, pw = t & 63;
    const int n  = ph * 64 + pw;
    const size_t obase = ((size_t)b * NPATCH + n) * KDIM + kh * 4;
    const float* xr = x + (((size_t)b * CIN) * 256 + ph * 4 + kh) * 256 + pw * 4;
#pragma unroll 4
    for (int ci = 0; ci < CIN; ci++) {
        float4 v = *(const float4*)(xr + (size_t)ci * 65536);
        uint32_t h0, l0, h1, l1;
        split2(v.x, v.y, h0, l0);
        split2(v.z, v.w, h1, l1);
        *(uint2*)(g_xh + obase + ci * 16) = make_uint2(h0, h1);
        *(uint2*)(g_xl + obase + ci * 16) = make_uint2(l0, l1);
    }
}

__global__ void __launch_bounds__(256)
split_w_kernel(const float* __restrict__ Wq, const float* __restrict__ Wk,
               const float* __restrict__ Wv)
{
    const int m = blockIdx.x, o = blockIdx.y, t = threadIdx.x;
    const float* W = (m == 0) ? Wq : (m == 1) ? Wk : Wv;
    float4 v = *(const float4*)(W + (size_t)o * KDIM + t * 4);
    uint32_t h0, l0, h1, l1;
    split2(v.x, v.y, h0, l0);
    split2(v.z, v.w, h1, l1);
    size_t ob = (size_t)m * COUT * KDIM + (size_t)o * KDIM + t * 4;
    *(uint2*)(g_wh + ob) = make_uint2(h0, h1);
    *(uint2*)(g_wl + ob) = make_uint2(l0, l1);
}

// ---------------------------------------------------------------------------
// conv as HMMA GEMM, k=64 double-buffered cp.async + B-frag register pipeline.
// ---------------------------------------------------------------------------
#define CSTR 144
#define CTSZ (128 * CSTR)
#define CONV_SMEM (8 * CTSZ)

__global__ void __launch_bounds__(256)
conv_mma_kernel(const float* __restrict__ bq, const float* __restrict__ bk,
                const float* __restrict__ bv)
{
    extern __shared__ char dsm[];
    const int tid = threadIdx.x;
    const int w   = tid >> 5;
    const int l   = tid & 31;
    const int n0  = blockIdx.x * 128;
    const int m   = blockIdx.y;
    const int b   = blockIdx.z;

    const uint32_t smb = smem_u32(dsm);
    const __nv_bfloat16* Ah = g_xh + ((size_t)b * NPATCH + n0) * KDIM;
    const __nv_bfloat16* Al = g_xl + ((size_t)b * NPATCH + n0) * KDIM;
    const __nv_bfloat16* Wh = g_wh + (size_t)m * COUT * KDIM;
    const __nv_bfloat16* Wl = g_wl + (size_t)m * COUT * KDIM;
    const float* bias = (m == 0) ? bq : (m == 1) ? bk : bv;

    const uint32_t aqoff = (uint32_t)((16 * w + (l & 15)) * CSTR + (l >> 4) * 16);
    const uint32_t boff4 = (uint32_t)((((l & 7) + ((l >> 4) << 3)) * CSTR) + (((l >> 3) & 1) << 4));

    float c[16][4];
#pragma unroll
    for (int nb = 0; nb < 16; nb++)
#pragma unroll
        for (int j = 0; j < 4; j++) c[nb][j] = 0.0f;

    auto prefetch = [&](int ch, int bf) {
        uint32_t bb = smb + (uint32_t)bf * 4 * CTSZ;
#pragma unroll
        for (int rep = 0; rep < 4; rep++) {
            int i = tid + rep * 256;
            int row = i >> 3, cc = i & 7;
            size_t g = (size_t)row * KDIM + ch * 64 + cc * 8;
            uint32_t d = (uint32_t)(row * CSTR + cc * 16);
            CP_ASYNC16(bb + 0 * CTSZ + d, Ah + g);
            CP_ASYNC16(bb + 1 * CTSZ + d, Al + g);
            CP_ASYNC16(bb + 2 * CTSZ + d, Wh + g);
            CP_ASYNC16(bb + 3 * CTSZ + d, Wl + g);
        }
    };

    prefetch(0, 0);
    CP_COMMIT();

    int bf = 0;
    for (int ch = 0; ch < 16; ch++) {
        CP_WAIT0();
        __syncthreads();
        if (ch < 15) { prefetch(ch + 1, bf ^ 1); CP_COMMIT(); }

        uint32_t bb = smb + (uint32_t)bf * 4 * CTSZ;
#pragma unroll
        for (int kc = 0; kc < 4; kc++) {
            uint32_t ah0, ah1, ah2, ah3, al0, al1, al2, al3;
            uint32_t qa = bb + aqoff + kc * 32;
            LDSM_X4(ah0, ah1, ah2, ah3, qa);
            LDSM_X4(al0, al1, al2, al3, qa + CTSZ);
            uint32_t wh[2][4], wl[2][4];
            {
                uint32_t ka = bb + 2 * CTSZ + boff4 + kc * 32;
                LDSM_X4(wh[0][0], wh[0][1], wh[0][2], wh[0][3], ka);
                LDSM_X4(wl[0][0], wl[0][1], wl[0][2], wl[0][3], ka + CTSZ);
            }
#pragma unroll
            for (int nb2 = 0; nb2 < 8; nb2++) {
                const int cur = nb2 & 1, nxt = cur ^ 1;
                if (nb2 < 7) {
                    uint32_t ka = bb + 2 * CTSZ + (nb2 + 1) * (16 * CSTR) + boff4 + kc * 32;
                    LDSM_X4(wh[nxt][0], wh[nxt][1], wh[nxt][2], wh[nxt][3], ka);
                    LDSM_X4(wl[nxt][0], wl[nxt][1], wl[nxt][2], wl[nxt][3], ka + CTSZ);
                }
                mma16816(c[2 * nb2],     ah0, ah1, ah2, ah3, wh[cur][0], wh[cur][1]);
                mma16816(c[2 * nb2],     al0, al1, al2, al3, wh[cur][0], wh[cur][1]);
                mma16816(c[2 * nb2],     ah0, ah1, ah2, ah3, wl[cur][0], wl[cur][1]);
                mma16816(c[2 * nb2 + 1], ah0, ah1, ah2, ah3, wh[cur][2], wh[cur][3]);
                mma16816(c[2 * nb2 + 1], al0, al1, al2, al3, wh[cur][2], wh[cur][3]);
                mma16816(c[2 * nb2 + 1], ah0, ah1, ah2, ah3, wl[cur][2], wl[cur][3]);
            }
        }
        bf ^= 1;
    }

    __syncthreads();
    {
        float* Cs = (float*)dsm;   // [128 n][136]
        int r0 = 16 * w + (l >> 2), r1 = r0 + 8;
#pragma unroll
        for (int nb = 0; nb < 16; nb++) {
            int cb = 8 * nb + 2 * (l & 3);
            float b0 = bias[cb], b1 = bias[cb + 1];
            Cs[r0 * 136 + cb]     = c[nb][0] + b0;
            Cs[r0 * 136 + cb + 1] = c[nb][1] + b1;
            Cs[r1 * 136 + cb]     = c[nb][2] + b0;
            Cs[r1 * 136 + cb + 1] = c[nb][3] + b1;
        }
    }
    __syncthreads();
    const float* Cs = (const float*)dsm;
    if (m < 2) {
        __nv_bfloat16* gh = (m == 0) ? g_qh : g_kh;
        __nv_bfloat16* gl = (m == 0) ? g_ql : g_kl;
        int n = tid >> 1, hf = tid & 1;
        size_t base = ((size_t)b * NPATCH + n0 + n) * COUT + hf * 64;
        const float* src = Cs + n * 136 + hf * 64;
#pragma unroll
        for (int j = 0; j < 8; j++) {
            uint32_t h[4], lo[4];
#pragma unroll
            for (int e = 0; e < 4; e++)
                split2(src[j * 8 + 2 * e], src[j * 8 + 2 * e + 1], h[e], lo[e]);
            *(uint4*)(gh + base + j * 8) = make_uint4(h[0], h[1], h[2], h[3]);
            *(uint4*)(gl + base + j * 8) = make_uint4(lo[0], lo[1], lo[2], lo[3]);
        }
    } else {
        int o = tid >> 1, hf = tid & 1;
        size_t base = ((size_t)b * COUT + o) * NPATCH + n0 + hf * 64;
        const float* src = Cs + (hf * 64) * 136 + o;
#pragma unroll
        for (int j = 0; j < 8; j++) {
            uint32_t h[4], lo[4];
#pragma unroll
            for (int e = 0; e < 4; e++)
                split2(src[(j * 8 + 2 * e) * 136], src[(j * 8 + 2 * e + 1) * 136], h[e], lo[e]);
            *(uint4*)(g_vh + base + j * 8) = make_uint4(h[0], h[1], h[2], h[3]);
            *(uint4*)(g_vl + base + j * 8) = make_uint4(lo[0], lo[1], lo[2], lo[3]);
        }
    }
}

// ---------------------------------------------------------------------------
// HMMA flash attention (R12 shape: 256 thr, 8 warps) + B-frag register
// pipeline in QK and PV: preload next nb2 group's LDSMs before current MMAs.
// ---------------------------------------------------------------------------
#define RSTR 272
#define TSZ  34816
#define SQH  0
#define SQL  (SQH + TSZ)
#define SKH  (SQL + TSZ)
#define SKL  (SKH + TSZ)
#define SVH  (SKL + TSZ)
#define SVL  (SVH + TSZ)
#define DSMEM (SVL + TSZ)  // 208896 bytes

__global__ void __launch_bounds__(256, 1)
attn_kernel(float* __restrict__ out)
{
    extern __shared__ char dsm[];
    const int tid = threadIdx.x;
    const int w   = tid >> 5;
    const int l   = tid & 31;
    const int b   = blockIdx.y;
    const int n0  = blockIdx.x * 128;

    const uint32_t smb = smem_u32(dsm);

    const __nv_bfloat16* qhp = g_qh + ((size_t)b * NPATCH + n0) * COUT;
    const __nv_bfloat16* qlp = g_ql + ((size_t)b * NPATCH + n0) * COUT;
    const __nv_bfloat16* khp = g_kh + (size_t)b * NPATCH * COUT;
    const __nv_bfloat16* klp = g_kl + (size_t)b * NPATCH * COUT;
    const __nv_bfloat16* vhp = g_vh + (size_t)b * COUT * NPATCH;
    const __nv_bfloat16* vlp = g_vl + (size_t)b * COUT * NPATCH;

    for (int i = tid; i < 2048; i += 256) {
        int row = i >> 4, c = i & 15;
        *(uint4*)(dsm + SQH + row * RSTR + c * 16) = *(const uint4*)(qhp + (size_t)row * COUT + c * 8);
        *(uint4*)(dsm + SQL + row * RSTR + c * 16) = *(const uint4*)(qlp + (size_t)row * COUT + c * 8);
    }
    for (int i = tid; i < 2048; i += 256) {
        int row = i >> 4, c = i & 15;
        uint32_t d = (uint32_t)(row * RSTR + c * 16);
        CP_ASYNC16(smb + SKH + d, khp + (size_t)row * COUT + c * 8);
        CP_ASYNC16(smb + SKL + d, klp + (size_t)row * COUT + c * 8);
    }
    CP_COMMIT();

    const uint32_t aqoff = (uint32_t)((16 * w + (l & 15)) * RSTR + (l >> 4) * 16);
    const uint32_t boff4 = (uint32_t)((((l & 7) + ((l >> 4) << 3)) * RSTR) + (((l >> 3) & 1) << 4));

    float s[16][4];
    float o[16][4];
#pragma unroll
    for (int nb = 0; nb < 16; nb++)
#pragma unroll
        for (int j = 0; j < 4; j++) o[nb][j] = 0.0f;
    float m0 = -1e30f, m1 = -1e30f, l0 = 0.0f, l1 = 0.0f;

    for (int it = 0; it < 32; it++) {
        CP_WAIT0();
        __syncthreads();

        // prefetch V_it under QK compute
        for (int i = tid; i < 2048; i += 256) {
            int row = i >> 4, c = i & 15;
            uint32_t d = (uint32_t)(row * RSTR + c * 16);
            size_t g = (size_t)row * NPATCH + it * 128 + c * 8;
            CP_ASYNC16(smb + SVH + d, vhp + g);
            CP_ASYNC16(smb + SVL + d, vlp + g);
        }
        CP_COMMIT();

        // ---- S = Q K^T (3x split), B-frag pipelined ----
#pragma unroll
        for (int nb = 0; nb < 16; nb++)
#pragma unroll
            for (int j = 0; j < 4; j++) s[nb][j] = 0.0f;

        for (int kc = 0; kc < 8; kc++) {
            uint32_t qh0, qh1, qh2, qh3, ql0, ql1, ql2, ql3;
            uint32_t qa = smb + SQH + aqoff + kc * 32;
            LDSM_X4(qh0, qh1, qh2, qh3, qa);
            LDSM_X4(ql0, ql1, ql2, ql3, qa + (SQL - SQH));
            uint32_t kh[2][4], kl[2][4];
            {
                uint32_t ka = smb + SKH + boff4 + kc * 32;
                LDSM_X4(kh[0][0], kh[0][1], kh[0][2], kh[0][3], ka);
                LDSM_X4(kl[0][0], kl[0][1], kl[0][2], kl[0][3], ka + (SKL - SKH));
            }
#pragma unroll
            for (int nb2 = 0; nb2 < 8; nb2++) {
                const int cur = nb2 & 1, nxt = cur ^ 1;
                if (nb2 < 7) {
                    uint32_t ka = smb + SKH + (nb2 + 1) * (16 * RSTR) + boff4 + kc * 32;
                    LDSM_X4(kh[nxt][0], kh[nxt][1], kh[nxt][2], kh[nxt][3], ka);
                    LDSM_X4(kl[nxt][0], kl[nxt][1], kl[nxt][2], kl[nxt][3], ka + (SKL - SKH));
                }
                mma16816(s[2 * nb2],     qh0, qh1, qh2, qh3, kh[cur][0], kh[cur][1]);
                mma16816(s[2 * nb2],     ql0, ql1, ql2, ql3, kh[cur][0], kh[cur][1]);
                mma16816(s[2 * nb2],     qh0, qh1, qh2, qh3, kl[cur][0], kl[cur][1]);
                mma16816(s[2 * nb2 + 1], qh0, qh1, qh2, qh3, kh[cur][2], kh[cur][3]);
                mma16816(s[2 * nb2 + 1], ql0, ql1, ql2, ql3, kh[cur][2], kh[cur][3]);
                mma16816(s[2 * nb2 + 1], qh0, qh1, qh2, qh3, kl[cur][2], kl[cur][3]);
            }
        }

        // ---- warp-local online softmax ----
        float mx0 = -1e30f, mx1 = -1e30f;
#pragma unroll
        for (int nb = 0; nb < 16; nb++) {
            mx0 = fmaxf(mx0, fmaxf(s[nb][0], s[nb][1]));
            mx1 = fmaxf(mx1, fmaxf(s[nb][2], s[nb][3]));
        }
        mx0 = fmaxf(mx0, __shfl_xor_sync(0xffffffffu, mx0, 1));
        mx0 = fmaxf(mx0, __shfl_xor_sync(0xffffffffu, mx0, 2));
        mx1 = fmaxf(mx1, __shfl_xor_sync(0xffffffffu, mx1, 1));
        mx1 = fmaxf(mx1, __shfl_xor_sync(0xffffffffu, mx1, 2));
        float nm0 = fmaxf(m0, mx0), nm1 = fmaxf(m1, mx1);
        float f0 = __expf(m0 - nm0), f1 = __expf(m1 - nm1);
        m0 = nm0; m1 = nm1;
        float sum0 = 0.0f, sum1 = 0.0f;
#pragma unroll
        for (int nb = 0; nb < 16; nb++) {
            s[nb][0] = __expf(s[nb][0] - nm0);
            s[nb][1] = __expf(s[nb][1] - nm0);
            s[nb][2] = __expf(s[nb][2] - nm1);
            s[nb][3] = __expf(s[nb][3] - nm1);
            sum0 += s[nb][0] + s[nb][1];
            sum1 += s[nb][2] + s[nb][3];
        }
        sum0 += __shfl_xor_sync(0xffffffffu, sum0, 1);
        sum0 += __shfl_xor_sync(0xffffffffu, sum0, 2);
        sum1 += __shfl_xor_sync(0xffffffffu, sum1, 1);
        sum1 += __shfl_xor_sync(0xffffffffu, sum1, 2);
        l0 = l0 * f0 + sum0;
        l1 = l1 * f1 + sum1;
#pragma unroll
        for (int nb = 0; nb < 16; nb++) {
            o[nb][0] *= f0; o[nb][1] *= f0;
            o[nb][2] *= f1; o[nb][3] *= f1;
        }

        CP_WAIT0();
        __syncthreads();

        // prefetch K_{it+1} under PV compute
        if (it < 31) {
            const __nv_bfloat16* ks  = khp + (size_t)((it + 1) * 128) * COUT;
            const __nv_bfloat16* ks2 = klp + (size_t)((it + 1) * 128) * COUT;
            for (int i = tid; i < 2048; i += 256) {
                int row = i >> 4, c = i & 15;
                uint32_t d = (uint32_t)(row * RSTR + c * 16);
                CP_ASYNC16(smb + SKH + d, ks  + (size_t)row * COUT + c * 8);
                CP_ASYNC16(smb + SKL + d, ks2 + (size_t)row * COUT + c * 8);
            }
        }
        CP_COMMIT();

        // ---- O += P V, B-frag pipelined (preload before split2 work) ----
#pragma unroll
        for (int mc = 0; mc < 8; mc++) {
            uint32_t vh[2][4], vl[2][4];
            {
                uint32_t va = smb + SVH + boff4 + mc * 32;
                LDSM_X4(vh[0][0], vh[0][1], vh[0][2], vh[0][3], va);
                LDSM_X4(vl[0][0], vl[0][1], vl[0][2], vl[0][3], va + (SVL - SVH));
            }
            uint32_t ah0, ah1, ah2, ah3, al0, al1, al2, al3;
            split2(s[2 * mc][0],     s[2 * mc][1],     ah0, al0);
            split2(s[2 * mc][2],     s[2 * mc][3],     ah1, al1);
            split2(s[2 * mc + 1][0], s[2 * mc + 1][1], ah2, al2);
            split2(s[2 * mc + 1][2], s[2 * mc + 1][3], ah3, al3);
#pragma unroll
            for (int nb2 = 0; nb2 < 8; nb2++) {
                const int cur = nb2 & 1, nxt = cur ^ 1;
                if (nb2 < 7) {
                    uint32_t va = smb + SVH + (nb2 + 1) * (16 * RSTR) + boff4 + mc * 32;
                    LDSM_X4(vh[nxt][0], vh[nxt][1], vh[nxt][2], vh[nxt][3], va);
                    LDSM_X4(vl[nxt][0], vl[nxt][1], vl[nxt][2], vl[nxt][3], va + (SVL - SVH));
                }
                mma16816(o[2 * nb2],     ah0, ah1, ah2, ah3, vh[cur][0], vh[cur][1]);
                mma16816(o[2 * nb2],     al0, al1, al2, al3, vh[cur][0], vh[cur][1]);
                mma16816(o[2 * nb2],     ah0, ah1, ah2, ah3, vl[cur][0], vl[cur][1]);
                mma16816(o[2 * nb2 + 1], ah0, ah1, ah2, ah3, vh[cur][2], vh[cur][3]);
                mma16816(o[2 * nb2 + 1], al0, al1, al2, al3, vh[cur][2], vh[cur][3]);
                mma16816(o[2 * nb2 + 1], ah0, ah1, ah2, ah3, vl[cur][2], vl[cur][3]);
            }
        }
    }

    // ---- epilogue: normalize, stage transpose in smem, coalesced write ----
    __syncthreads();
    {
        float inv0 = 1.0f / l0, inv1 = 1.0f / l1;
        int r0 = 16 * w + (l >> 2), r1 = r0 + 8;
        float* Os = (float*)dsm;
#pragma unroll
        for (int nb = 0; nb < 16; nb++) {
            int cb = 8 * nb + 2 * (l & 3);
            Os[cb * 132 + r0]       = o[nb][0] * inv0;
            Os[(cb + 1) * 132 + r0] = o[nb][1] * inv0;
            Os[cb * 132 + r1]       = o[nb][2] * inv1;
            Os[(cb + 1) * 132 + r1] = o[nb][3] * inv1;
        }
    }
    __syncthreads();
    {
        int oc = tid >> 1, hseg = tid & 1;
        float* ob = out + ((size_t)b * COUT + oc) * NPATCH + n0 + hseg * 64;
        const float* src = (const float*)dsm + oc * 132 + hseg * 64;
#pragma unroll
        for (int w4 = 0; w4 < 16; w4++)
            *(float4*)(ob + w4 * 4) = *(const float4*)(src + w4 * 4);
    }
}

extern "C" void kernel_launch(void* const* d_in, const int* in_sizes, int n_in,
                              void* d_out, int out_size)
{
    (void)in_sizes; (void)n_in; (void)out_size;
    const float* x  = (const float*)d_in[0];
    const float* Wq = (const float*)d_in[1];
    const float* bq = (const float*)d_in[2];
    const float* Wk = (const float*)d_in[3];
    const float* bk = (const float*)d_in[4];
    const float* Wv = (const float*)d_in[5];
    const float* bv = (const float*)d_in[6];
    float* out = (float*)d_out;

    cudaFuncSetAttribute(conv_mma_kernel, cudaFuncAttributeMaxDynamicSharedMemorySize, CONV_SMEM);
    cudaFuncSetAttribute(attn_kernel, cudaFuncAttributeMaxDynamicSharedMemorySize, DSMEM);

    split_x_kernel<<<dim3(64, NB), 256>>>(x);
    split_w_kernel<<<dim3(3, COUT), 256>>>(Wq, Wk, Wv);
    conv_mma_kernel<<<dim3(NPATCH / 128, 3, NB), 256, CONV_SMEM>>>(bq, bk, bv);
    attn_kernel<<<dim3(NPATCH / 128, NB), 256, DSMEM>>>(out);
}

// round 15
// speedup vs baseline: 1.5313x; 1.5313x over previous
#include <cuda_runtime.h>
#include <cuda_bf16.h>
#include <cstdint>

#define NB     4
#define CIN    64
#define COUT   128
#define NPATCH 4096
#define KDIM   1024

// im2col + split operands
__device__ __nv_bfloat16 g_xh[NB * NPATCH * KDIM];   // [b][n][k]
__device__ __nv_bfloat16 g_xl[NB * NPATCH * KDIM];
__device__ __nv_bfloat16 g_wh[3 * COUT * KDIM];      // [mat][o][k]
__device__ __nv_bfloat16 g_wl[3 * COUT * KDIM];
// q/k/v split operands produced by conv_mma
__device__ __nv_bfloat16 g_qh[NB * NPATCH * COUT];   // [b][n][o]
__device__ __nv_bfloat16 g_ql[NB * NPATCH * COUT];
__device__ __nv_bfloat16 g_kh[NB * NPATCH * COUT];   // [b][n][o]
__device__ __nv_bfloat16 g_kl[NB * NPATCH * COUT];
__device__ __nv_bfloat16 g_vh[NB * COUT * NPATCH];   // [b][o][n]  (transposed)
__device__ __nv_bfloat16 g_vl[NB * COUT * NPATCH];

// ---------------- warp-level tensor core helpers (baseline PTX, sm_80+) ------
#define LDSM_X4(r0, r1, r2, r3, addr) \
    asm volatile("ldmatrix.sync.aligned.m8n8.x4.shared.b16 {%0,%1,%2,%3}, [%4];" \
        : "=r"(r0), "=r"(r1), "=r"(r2), "=r"(r3) : "r"(addr))
#define CP_ASYNC16(saddr, gptr) \
    asm volatile("cp.async.cg.shared.global [%0], [%1], 16;" :: "r"(saddr), "l"(gptr))
#define CP_COMMIT() asm volatile("cp.async.commit_group;" ::: "memory")
#define CP_WAIT0()  asm volatile("cp.async.wait_group 0;" ::: "memory")

__device__ __forceinline__ void mma16816(float c[4],
    uint32_t a0, uint32_t a1, uint32_t a2, uint32_t a3,
    uint32_t b0, uint32_t b1)
{
    asm volatile(
        "mma.sync.aligned.m16n8k16.row.col.f32.bf16.bf16.f32 "
        "{%0,%1,%2,%3}, {%4,%5,%6,%7}, {%8,%9}, {%0,%1,%2,%3};"
        : "+f"(c[0]), "+f"(c[1]), "+f"(c[2]), "+f"(c[3])
        : "r"(a0), "r"(a1), "r"(a2), "r"(a3), "r"(b0), "r"(b1));
}

__device__ __forceinline__ uint32_t smem_u32(const void* p) {
    uint32_t a;
    asm("{ .reg .u64 t; cvta.to.shared.u64 t, %1; cvt.u32.u64 %0, t; }" : "=r"(a) : "l"(p));
    return a;
}
// split two fp32 into bf16x2 hi + bf16x2 lo (residual)
__device__ __forceinline__ void split2(float x, float y, uint32_t& hi, uint32_t& lo) {
    __nv_bfloat16 hx = __float2bfloat16(x), hy = __float2bfloat16(y);
    __nv_bfloat162 h2(hx, hy);
    __nv_bfloat162 l2(__float2bfloat16(x - __bfloat162float(hx)),
                      __float2bfloat16(y - __bfloat162float(hy)));
    hi = *(uint32_t*)&h2;
    lo = *(uint32_t*)&l2;
}

// ---------------------------------------------------------------------------
// split_x / split_w  (unchanged)
// ---------------------------------------------------------------------------
__global__ void __launch_bounds__(256)
split_x_kernel(const float* __restrict__ x)
{
    const int ph = blockIdx.x, b = blockIdx.y;
    const int t  = threadIdx.x;
    const int kh = t >> 6, pw = t & 63;
    const int n  = ph * 64 + pw;
    const size_t obase = ((size_t)b * NPATCH + n) * KDIM + kh * 4;
    const float* xr = x + (((size_t)b * CIN) * 256 + ph * 4 + kh) * 256 + pw * 4;
#pragma unroll 4
    for (int ci = 0; ci < CIN; ci++) {
        float4 v = *(const float4*)(xr + (size_t)ci * 65536);
        uint32_t h0, l0, h1, l1;
        split2(v.x, v.y, h0, l0);
        split2(v.z, v.w, h1, l1);
        *(uint2*)(g_xh + obase + ci * 16) = make_uint2(h0, h1);
        *(uint2*)(g_xl + obase + ci * 16) = make_uint2(l0, l1);
    }
}

__global__ void __launch_bounds__(256)
split_w_kernel(const float* __restrict__ Wq, const float* __restrict__ Wk,
               const float* __restrict__ Wv)
{
    const int m = blockIdx.x, o = blockIdx.y, t = threadIdx.x;
    const float* W = (m == 0) ? Wq : (m == 1) ? Wk : Wv;
    float4 v = *(const float4*)(W + (size_t)o * KDIM + t * 4);
    uint32_t h0, l0, h1, l1;
    split2(v.x, v.y, h0, l0);
    split2(v.z, v.w, h1, l1);
    size_t ob = (size_t)m * COUT * KDIM + (size_t)o * KDIM + t * 4;
    *(uint2*)(g_wh + ob) = make_uint2(h0, h1);
    *(uint2*)(g_wl + ob) = make_uint2(l0, l1);
}

// ---------------------------------------------------------------------------
// conv as HMMA GEMM (unchanged from R14)
// ---------------------------------------------------------------------------
#define CSTR 144
#define CTSZ (128 * CSTR)
#define CONV_SMEM (8 * CTSZ)

__global__ void __launch_bounds__(256)
conv_mma_kernel(const float* __restrict__ bq, const float* __restrict__ bk,
                const float* __restrict__ bv)
{
    extern __shared__ char dsm[];
    const int tid = threadIdx.x;
    const int w   = tid >> 5;
    const int l   = tid & 31;
    const int n0  = blockIdx.x * 128;
    const int m   = blockIdx.y;
    const int b   = blockIdx.z;

    const uint32_t smb = smem_u32(dsm);
    const __nv_bfloat16* Ah = g_xh + ((size_t)b * NPATCH + n0) * KDIM;
    const __nv_bfloat16* Al = g_xl + ((size_t)b * NPATCH + n0) * KDIM;
    const __nv_bfloat16* Wh = g_wh + (size_t)m * COUT * KDIM;
    const __nv_bfloat16* Wl = g_wl + (size_t)m * COUT * KDIM;
    const float* bias = (m == 0) ? bq : (m == 1) ? bk : bv;

    const uint32_t aqoff = (uint32_t)((16 * w + (l & 15)) * CSTR + (l >> 4) * 16);
    const uint32_t boff4 = (uint32_t)((((l & 7) + ((l >> 4) << 3)) * CSTR) + (((l >> 3) & 1) << 4));

    float c[16][4];
#pragma unroll
    for (int nb = 0; nb < 16; nb++)
#pragma unroll
        for (int j = 0; j < 4; j++) c[nb][j] = 0.0f;

    auto prefetch = [&](int ch, int bf) {
        uint32_t bb = smb + (uint32_t)bf * 4 * CTSZ;
#pragma unroll
        for (int rep = 0; rep < 4; rep++) {
            int i = tid + rep * 256;
            int row = i >> 3, cc = i & 7;
            size_t g = (size_t)row * KDIM + ch * 64 + cc * 8;
            uint32_t d = (uint32_t)(row * CSTR + cc * 16);
            CP_ASYNC16(bb + 0 * CTSZ + d, Ah + g);
            CP_ASYNC16(bb + 1 * CTSZ + d, Al + g);
            CP_ASYNC16(bb + 2 * CTSZ + d, Wh + g);
            CP_ASYNC16(bb + 3 * CTSZ + d, Wl + g);
        }
    };

    prefetch(0, 0);
    CP_COMMIT();

    int bf = 0;
    for (int ch = 0; ch < 16; ch++) {
        CP_WAIT0();
        __syncthreads();
        if (ch < 15) { prefetch(ch + 1, bf ^ 1); CP_COMMIT(); }

        uint32_t bb = smb + (uint32_t)bf * 4 * CTSZ;
#pragma unroll
        for (int kc = 0; kc < 4; kc++) {
            uint32_t ah0, ah1, ah2, ah3, al0, al1, al2, al3;
            uint32_t qa = bb + aqoff + kc * 32;
            LDSM_X4(ah0, ah1, ah2, ah3, qa);
            LDSM_X4(al0, al1, al2, al3, qa + CTSZ);
#pragma unroll
            for (int nb2 = 0; nb2 < 8; nb2++) {
                uint32_t ka = bb + 2 * CTSZ + nb2 * (16 * CSTR) + boff4 + kc * 32;
                uint32_t wh0, wh1, wh2, wh3, wl0, wl1, wl2, wl3;
                LDSM_X4(wh0, wh1, wh2, wh3, ka);
                LDSM_X4(wl0, wl1, wl2, wl3, ka + CTSZ);
                mma16816(c[2 * nb2],     ah0, ah1, ah2, ah3, wh0, wh1);
                mma16816(c[2 * nb2],     al0, al1, al2, al3, wh0, wh1);
                mma16816(c[2 * nb2],     ah0, ah1, ah2, ah3, wl0, wl1);
                mma16816(c[2 * nb2 + 1], ah0, ah1, ah2, ah3, wh2, wh3);
                mma16816(c[2 * nb2 + 1], al0, al1, al2, al3, wh2, wh3);
                mma16816(c[2 * nb2 + 1], ah0, ah1, ah2, ah3, wl2, wl3);
            }
        }
        bf ^= 1;
    }

    __syncthreads();
    {
        float* Cs = (float*)dsm;   // [128 n][136]
        int r0 = 16 * w + (l >> 2), r1 = r0 + 8;
#pragma unroll
        for (int nb = 0; nb < 16; nb++) {
            int cb = 8 * nb + 2 * (l & 3);
            float b0 = bias[cb], b1 = bias[cb + 1];
            Cs[r0 * 136 + cb]     = c[nb][0] + b0;
            Cs[r0 * 136 + cb + 1] = c[nb][1] + b1;
            Cs[r1 * 136 + cb]     = c[nb][2] + b0;
            Cs[r1 * 136 + cb + 1] = c[nb][3] + b1;
        }
    }
    __syncthreads();
    const float* Cs = (const float*)dsm;
    if (m < 2) {
        __nv_bfloat16* gh = (m == 0) ? g_qh : g_kh;
        __nv_bfloat16* gl = (m == 0) ? g_ql : g_kl;
        int n = tid >> 1, hf = tid & 1;
        size_t base = ((size_t)b * NPATCH + n0 + n) * COUT + hf * 64;
        const float* src = Cs + n * 136 + hf * 64;
#pragma unroll
        for (int j = 0; j < 8; j++) {
            uint32_t h[4], lo[4];
#pragma unroll
            for (int e = 0; e < 4; e++)
                split2(src[j * 8 + 2 * e], src[j * 8 + 2 * e + 1], h[e], lo[e]);
            *(uint4*)(gh + base + j * 8) = make_uint4(h[0], h[1], h[2], h[3]);
            *(uint4*)(gl + base + j * 8) = make_uint4(lo[0], lo[1], lo[2], lo[3]);
        }
    } else {
        int o = tid >> 1, hf = tid & 1;
        size_t base = ((size_t)b * COUT + o) * NPATCH + n0 + hf * 64;
        const float* src = Cs + (hf * 64) * 136 + o;
#pragma unroll
        for (int j = 0; j < 8; j++) {
            uint32_t h[4], lo[4];
#pragma unroll
            for (int e = 0; e < 4; e++)
                split2(src[(j * 8 + 2 * e) * 136], src[(j * 8 + 2 * e + 1) * 136], h[e], lo[e]);
            *(uint4*)(g_vh + base + j * 8) = make_uint4(h[0], h[1], h[2], h[3]);
            *(uint4*)(g_vl + base + j * 8) = make_uint4(lo[0], lo[1], lo[2], lo[3]);
        }
    }
}

// ---------------------------------------------------------------------------
// HMMA flash attention, 256 thr. Softmax FUSED into the PV loop: after the
// V-ready sync, each 8-key group's exp/split2/sum issues right before its PV
// MMAs so MUFU/ALU work hides in tensor-pipe gaps. Only the row-max reduce
// and o-rescale remain serial between QK and PV.
// ---------------------------------------------------------------------------
#define RSTR 272
#define TSZ  34816
#define SQH  0
#define SQL  (SQH + TSZ)
#define SKH  (SQL + TSZ)
#define SKL  (SKH + TSZ)
#define SVH  (SKL + TSZ)
#define SVL  (SVH + TSZ)
#define DSMEM (SVL + TSZ)  // 208896 bytes

__global__ void __launch_bounds__(256, 1)
attn_kernel(float* __restrict__ out)
{
    extern __shared__ char dsm[];
    const int tid = threadIdx.x;
    const int w   = tid >> 5;
    const int l   = tid & 31;
    const int b   = blockIdx.y;
    const int n0  = blockIdx.x * 128;

    const uint32_t smb = smem_u32(dsm);

    const __nv_bfloat16* qhp = g_qh + ((size_t)b * NPATCH + n0) * COUT;
    const __nv_bfloat16* qlp = g_ql + ((size_t)b * NPATCH + n0) * COUT;
    const __nv_bfloat16* khp = g_kh + (size_t)b * NPATCH * COUT;
    const __nv_bfloat16* klp = g_kl + (size_t)b * NPATCH * COUT;
    const __nv_bfloat16* vhp = g_vh + (size_t)b * COUT * NPATCH;
    const __nv_bfloat16* vlp = g_vl + (size_t)b * COUT * NPATCH;

    for (int i = tid; i < 2048; i += 256) {
        int row = i >> 4, c = i & 15;
        *(uint4*)(dsm + SQH + row * RSTR + c * 16) = *(const uint4*)(qhp + (size_t)row * COUT + c * 8);
        *(uint4*)(dsm + SQL + row * RSTR + c * 16) = *(const uint4*)(qlp + (size_t)row * COUT + c * 8);
    }
    for (int i = tid; i < 2048; i += 256) {
        int row = i >> 4, c = i & 15;
        uint32_t d = (uint32_t)(row * RSTR + c * 16);
        CP_ASYNC16(smb + SKH + d, khp + (size_t)row * COUT + c * 8);
        CP_ASYNC16(smb + SKL + d, klp + (size_t)row * COUT + c * 8);
    }
    CP_COMMIT();

    const uint32_t aqoff = (uint32_t)((16 * w + (l & 15)) * RSTR + (l >> 4) * 16);
    const uint32_t boff4 = (uint32_t)((((l & 7) + ((l >> 4) << 3)) * RSTR) + (((l >> 3) & 1) << 4));

    float s[16][4];
    float o[16][4];
#pragma unroll
    for (int nb = 0; nb < 16; nb++)
#pragma unroll
        for (int j = 0; j < 4; j++) o[nb][j] = 0.0f;
    float m0 = -1e30f, m1 = -1e30f, l0 = 0.0f, l1 = 0.0f;

    for (int it = 0; it < 32; it++) {
        CP_WAIT0();
        __syncthreads();

        // prefetch V_it under QK compute
        for (int i = tid; i < 2048; i += 256) {
            int row = i >> 4, c = i & 15;
            uint32_t d = (uint32_t)(row * RSTR + c * 16);
            size_t g = (size_t)row * NPATCH + it * 128 + c * 8;
            CP_ASYNC16(smb + SVH + d, vhp + g);
            CP_ASYNC16(smb + SVL + d, vlp + g);
        }
        CP_COMMIT();

        // ---- S = Q K^T (3x split) ----
#pragma unroll
        for (int nb = 0; nb < 16; nb++)
#pragma unroll
            for (int j = 0; j < 4; j++) s[nb][j] = 0.0f;

        for (int kc = 0; kc < 8; kc++) {
            uint32_t qh0, qh1, qh2, qh3, ql0, ql1, ql2, ql3;
            uint32_t qa = smb + SQH + aqoff + kc * 32;
            LDSM_X4(qh0, qh1, qh2, qh3, qa);
            LDSM_X4(ql0, ql1, ql2, ql3, qa + (SQL - SQH));
#pragma unroll
            for (int nb2 = 0; nb2 < 8; nb2++) {
                uint32_t ka = smb + SKH + nb2 * (16 * RSTR) + boff4 + kc * 32;
                uint32_t kh0, kh1, kh2, kh3, kl0, kl1, kl2, kl3;
                LDSM_X4(kh0, kh1, kh2, kh3, ka);
                LDSM_X4(kl0, kl1, kl2, kl3, ka + (SKL - SKH));
                mma16816(s[2 * nb2],     qh0, qh1, qh2, qh3, kh0, kh1);
                mma16816(s[2 * nb2],     ql0, ql1, ql2, ql3, kh0, kh1);
                mma16816(s[2 * nb2],     qh0, qh1, qh2, qh3, kl0, kl1);
                mma16816(s[2 * nb2 + 1], qh0, qh1, qh2, qh3, kh2, kh3);
                mma16816(s[2 * nb2 + 1], ql0, ql1, ql2, ql3, kh2, kh3);
                mma16816(s[2 * nb2 + 1], qh0, qh1, qh2, qh3, kl2, kl3);
            }
        }

        // ---- row-max reduce + o rescale (the only serial softmax part) ----
        float mx0 = -1e30f, mx1 = -1e30f;
#pragma unroll
        for (int nb = 0; nb < 16; nb++) {
            mx0 = fmaxf(mx0, fmaxf(s[nb][0], s[nb][1]));
            mx1 = fmaxf(mx1, fmaxf(s[nb][2], s[nb][3]));
        }
        mx0 = fmaxf(mx0, __shfl_xor_sync(0xffffffffu, mx0, 1));
        mx0 = fmaxf(mx0, __shfl_xor_sync(0xffffffffu, mx0, 2));
        mx1 = fmaxf(mx1, __shfl_xor_sync(0xffffffffu, mx1, 1));
        mx1 = fmaxf(mx1, __shfl_xor_sync(0xffffffffu, mx1, 2));
        float nm0 = fmaxf(m0, mx0), nm1 = fmaxf(m1, mx1);
        float f0 = __expf(m0 - nm0), f1 = __expf(m1 - nm1);
        m0 = nm0; m1 = nm1;
#pragma unroll
        for (int nb = 0; nb < 16; nb++) {
            o[nb][0] *= f0; o[nb][1] *= f0;
            o[nb][2] *= f1; o[nb][3] *= f1;
        }

        CP_WAIT0();
        __syncthreads();

        // prefetch K_{it+1} under PV compute
        if (it < 31) {
            const __nv_bfloat16* ks  = khp + (size_t)((it + 1) * 128) * COUT;
            const __nv_bfloat16* ks2 = klp + (size_t)((it + 1) * 128) * COUT;
            for (int i = tid; i < 2048; i += 256) {
                int row = i >> 4, c = i & 15;
                uint32_t d = (uint32_t)(row * RSTR + c * 16);
                CP_ASYNC16(smb + SKH + d, ks  + (size_t)row * COUT + c * 8);
                CP_ASYNC16(smb + SKL + d, ks2 + (size_t)row * COUT + c * 8);
            }
        }
        CP_COMMIT();

        // ---- FUSED exp + split + sum + PV MMAs per 8-key group ----
        float sum0 = 0.0f, sum1 = 0.0f;
#pragma unroll
        for (int mc = 0; mc < 8; mc++) {
            float p00 = __expf(s[2 * mc][0]     - nm0);
            float p01 = __expf(s[2 * mc][1]     - nm0);
            float p02 = __expf(s[2 * mc][2]     - nm1);
            float p03 = __expf(s[2 * mc][3]     - nm1);
            float p10 = __expf(s[2 * mc + 1][0] - nm0);
            float p11 = __expf(s[2 * mc + 1][1] - nm0);
            float p12 = __expf(s[2 * mc + 1][2] - nm1);
            float p13 = __expf(s[2 * mc + 1][3] - nm1);
            sum0 += p00 + p01 + p10 + p11;
            sum1 += p02 + p03 + p12 + p13;
            uint32_t ah0, ah1, ah2, ah3, al0, al1, al2, al3;
            split2(p00, p01, ah0, al0);
            split2(p02, p03, ah1, al1);
            split2(p10, p11, ah2, al2);
            split2(p12, p13, ah3, al3);
#pragma unroll
            for (int nb2 = 0; nb2 < 8; nb2++) {
                uint32_t va = smb + SVH + nb2 * (16 * RSTR) + boff4 + mc * 32;
                uint32_t vh0, vh1, vh2, vh3, vl0, vl1, vl2, vl3;
                LDSM_X4(vh0, vh1, vh2, vh3, va);
                LDSM_X4(vl0, vl1, vl2, vl3, va + (SVL - SVH));
                mma16816(o[2 * nb2],     ah0, ah1, ah2, ah3, vh0, vh1);
                mma16816(o[2 * nb2],     al0, al1, al2, al3, vh0, vh1);
                mma16816(o[2 * nb2],     ah0, ah1, ah2, ah3, vl0, vl1);
                mma16816(o[2 * nb2 + 1], ah0, ah1, ah2, ah3, vh2, vh3);
                mma16816(o[2 * nb2 + 1], al0, al1, al2, al3, vh2, vh3);
                mma16816(o[2 * nb2 + 1], ah0, ah1, ah2, ah3, vl2, vl3);
            }
        }
        sum0 += __shfl_xor_sync(0xffffffffu, sum0, 1);
        sum0 += __shfl_xor_sync(0xffffffffu, sum0, 2);
        sum1 += __shfl_xor_sync(0xffffffffu, sum1, 1);
        sum1 += __shfl_xor_sync(0xffffffffu, sum1, 2);
        l0 = l0 * f0 + sum0;
        l1 = l1 * f1 + sum1;
    }

    // ---- epilogue: normalize, stage transpose in smem, coalesced write ----
    __syncthreads();
    {
        float inv0 = 1.0f / l0, inv1 = 1.0f / l1;
        int r0 = 16 * w + (l >> 2), r1 = r0 + 8;
        float* Os = (float*)dsm;
#pragma unroll
        for (int nb = 0; nb < 16; nb++) {
            int cb = 8 * nb + 2 * (l & 3);
            Os[cb * 132 + r0]       = o[nb][0] * inv0;
            Os[(cb + 1) * 132 + r0] = o[nb][1] * inv0;
            Os[cb * 132 + r1]       = o[nb][2] * inv1;
            Os[(cb + 1) * 132 + r1] = o[nb][3] * inv1;
        }
    }
    __syncthreads();
    {
        int oc = tid >> 1, hseg = tid & 1;
        float* ob = out + ((size_t)b * COUT + oc) * NPATCH + n0 + hseg * 64;
        const float* src = (const float*)dsm + oc * 132 + hseg * 64;
#pragma unroll
        for (int w4 = 0; w4 < 16; w4++)
            *(float4*)(ob + w4 * 4) = *(const float4*)(src + w4 * 4);
    }
}

extern "C" void kernel_launch(void* const* d_in, const int* in_sizes, int n_in,
                              void* d_out, int out_size)
{
    (void)in_sizes; (void)n_in; (void)out_size;
    const float* x  = (const float*)d_in[0];
    const float* Wq = (const float*)d_in[1];
    const float* bq = (const float*)d_in[2];
    const float* Wk = (const float*)d_in[3];
    const float* bk = (const float*)d_in[4];
    const float* Wv = (const float*)d_in[5];
    const float* bv = (const float*)d_in[6];
    float* out = (float*)d_out;

    cudaFuncSetAttribute(conv_mma_kernel, cudaFuncAttributeMaxDynamicSharedMemorySize, CONV_SMEM);
    cudaFuncSetAttribute(attn_kernel, cudaFuncAttributeMaxDynamicSharedMemorySize, DSMEM);

    split_x_kernel<<<dim3(64, NB), 256>>>(x);
    split_w_kernel<<<dim3(3, COUT), 256>>>(Wq, Wk, Wv);
    conv_mma_kernel<<<dim3(NPATCH / 128, 3, NB), 256, CONV_SMEM>>>(bq, bk, bv);
    attn_kernel<<<dim3(NPATCH / 128, NB), 256, DSMEM>>>(out);
}